// round 14
// baseline (speedup 1.0000x reference)
#include <cuda_runtime.h>
#include <cstdint>
#include <math.h>

// ---------------- Problem constants ----------------
#define MROWS 10000
#define NFEAT 512
#define HID   64
#define MTILES 79
#define SEGS  (2 * MTILES)      // 158
#define NC    592               // persistent CTAs = 148 SMs x 4
#define PSLOTS 5                // max partial pieces per segment

// ---------------- GEMM tiling ----------------
#define BM 128
#define BN 64
#define BK2 32                  // k per tile (2 stages)
#define AP 36                   // padded row stride in floats (144B, 16B-mult, LDSM conflict-free)
#define A_BYTES (128 * AP * 4)  // 18432
#define B_BYTES (64 * AP * 4)   // 9216
#define STAGE_B (A_BYTES + B_BYTES)   // 27648
#define SMEM_G (2 * STAGE_B)          // 55296 (x4 CTAs = 221KB/SM)

// GEMM1: x@W  K=512  -> 16 tiles/seg.  GEMM2: adj@xw K=10000 -> 313 tiles/seg (last half).
#define KT1 16
#define TOT1 ((long long)SEGS * KT1)    // 2528
#define KT2 313
#define TOT2 ((long long)SEGS * KT2)    // 49454

// ---------------- Scratch ----------------
__device__ __align__(16) float g_xwT[2 * HID * MROWS];           // xw transposed (n-major), tf32
__device__ __align__(16) float g_wT[2 * HID * NFEAT];            // W transposed (n-major), tf32
__device__ __align__(16) float g_part[SEGS * PSLOTS * BM * HID]; // piece partials (25.9MB)
__device__ __align__(16) float g_emb[MROWS * HID];               // fallback emb

// ---------------- helpers ----------------
__device__ __forceinline__ uint32_t f2tf(float x) {
    uint32_t u; asm("cvt.rna.tf32.f32 %0, %1;" : "=r"(u) : "f"(x)); return u;
}
__device__ __forceinline__ int g_of(long long T, long long TOTAL) {
    return (int)(((T + 1) * NC - 1) / TOTAL);
}
__device__ __forceinline__ void cp16(uint32_t dst, const void* src, bool v) {
    const int sz = v ? 16 : 0;
    asm volatile("cp.async.cg.shared.global [%0], [%1], 16, %2;\n" :: "r"(dst), "l"(src), "r"(sz));
}
__device__ __forceinline__ void cp_commit() { asm volatile("cp.async.commit_group;\n"); }
__device__ __forceinline__ void cp_wait1()  { asm volatile("cp.async.wait_group 1;\n"); }
__device__ __forceinline__ void cp_wait0()  { asm volatile("cp.async.wait_group 0;\n"); }

__device__ __forceinline__ void ldsm4(uint32_t& d0, uint32_t& d1, uint32_t& d2, uint32_t& d3,
                                      uint32_t a) {
    asm volatile("ldmatrix.sync.aligned.m8n8.x4.shared.b16 {%0,%1,%2,%3}, [%4];"
                 : "=r"(d0), "=r"(d1), "=r"(d2), "=r"(d3) : "r"(a));
}
__device__ __forceinline__ void mma8(float& c0, float& c1, float& c2, float& c3,
                                     uint32_t a0, uint32_t a1, uint32_t a2, uint32_t a3,
                                     uint32_t b0, uint32_t b1) {
    asm("mma.sync.aligned.m16n8k8.row.col.f32.tf32.tf32.f32 "
        "{%0,%1,%2,%3}, {%4,%5,%6,%7}, {%8,%9}, {%0,%1,%2,%3};"
        : "+f"(c0), "+f"(c1), "+f"(c2), "+f"(c3)
        : "r"(a0), "r"(a1), "r"(a2), "r"(a3), "r"(b0), "r"(b1));
}

// ---------------- prep: W -> tf32, transposed to n-major [2][64][512] ----------------
__global__ void prep_wT_kernel(const float* __restrict__ W1, const float* __restrict__ W2,
                               float* __restrict__ wT)
{
    const int i = blockIdx.x * blockDim.x + threadIdx.x;
    if (i < NFEAT * HID) {
        const int k = i >> 6, n = i & 63;
        wT[n * NFEAT + k]               = __uint_as_float(f2tf(W1[i]));
        wT[HID * NFEAT + n * NFEAT + k] = __uint_as_float(f2tf(W2[i]));
    }
}

// ---------------- unified persistent GEMM (ldmatrix tf32) ----------------
// C-piece = A_br[m-tile, k-range] @ B_br^T where B stored n-major [64 x Ktot].
// A fragments +0x1000 (HW truncation -> RNA); B pre-rounded tf32.
__global__ __launch_bounds__(256, 4)
void gemm_ldsm(const float* __restrict__ A0, const float* __restrict__ A1,
               const float* __restrict__ B0, const float* __restrict__ B1,
               float* __restrict__ part, int M, long long lda, long long ldb,
               int Ktot, int KT, long long TOTAL)
{
    extern __shared__ __align__(128) char smem[];
    const uint32_t sb = (uint32_t)__cvta_generic_to_shared(smem);

    const int g = blockIdx.x;
    const long long rngS = ((long long)g * TOTAL) / NC;
    const long long rngE = ((long long)(g + 1) * TOTAL) / NC;
    const int len = (int)(rngE - rngS);
    if (len <= 0) return;

    const int tid  = threadIdx.x;
    const int lane = tid & 31;
    const int warp = tid >> 5;
    const int wm0  = (warp & 3) * 32;
    const int wn0  = (warp >> 2) * 32;
    const int r    = lane >> 2;
    const int c    = lane & 3;
    const int matid = lane >> 3;
    const int rr    = lane & 7;

    // LDSM per-lane base offsets (bytes, excluding stage base)
    const uint32_t aAddr0 = ((wm0 + (matid & 1) * 8 + rr) * AP + ((matid >> 1) * 4)) * 4;
    const uint32_t bAddr0 = (uint32_t)A_BYTES +
                            ((wn0 + (matid >> 1) * 8 + rr) * AP + ((matid & 1) * 4)) * 4;

    // staging maps
    const int aRow = tid >> 1;          // 0..127
    const int aC0  = (tid & 1) * 4;     // chunk 0..7 (16B each)
    const int bRow = tid >> 2;          // 0..63
    const int bC0  = (tid & 3) * 2;
    const uint32_t dA = sb + aRow * (AP * 4) + aC0 * 16;
    const uint32_t dB = sb + A_BYTES + bRow * (AP * 4) + bC0 * 16;

    // counters: prefetch (sP,kP) and compute (sC,kC)
    int sP = (int)(rngS / KT), kP = (int)(rngS % KT);
    int sC = sP, kC = kP;

    float acc[2][4][4];
#pragma unroll
    for (int a = 0; a < 2; ++a)
#pragma unroll
        for (int b = 0; b < 4; ++b)
#pragma unroll
            for (int d = 0; d < 4; ++d) acc[a][b][d] = 0.f;

    // ---- issue one tile's loads into stage, advance (sP,kP) ----
#define ISSUE(stage) do {                                                          \
    const float* A_ = (sP >= MTILES) ? A1 : A0;                                    \
    const float* B_ = (sP >= MTILES) ? B1 : B0;                                    \
    const int m0_ = (sP - ((sP >= MTILES) ? MTILES : 0)) * BM;                     \
    const int kB_ = kP * BK2;                                                      \
    const int row_ = m0_ + aRow;                                                   \
    const bool rv_ = row_ < M;                                                     \
    const float* sA_ = A_ + (size_t)(rv_ ? row_ : 0) * lda + kB_;                  \
    const float* sB_ = B_ + (size_t)bRow * ldb + kB_;                              \
    const uint32_t so_ = (stage) * (uint32_t)STAGE_B;                              \
    _Pragma("unroll")                                                              \
    for (int i_ = 0; i_ < 4; ++i_) {                                               \
        const int cc_ = aC0 + i_;                                                  \
        cp16(dA + so_ + i_ * 16, sA_ + 4 * cc_, rv_ && (kB_ + 4 * cc_ < Ktot));    \
    }                                                                              \
    _Pragma("unroll")                                                              \
    for (int i_ = 0; i_ < 2; ++i_) {                                               \
        const int cc_ = bC0 + i_;                                                  \
        cp16(dB + so_ + i_ * 16, sB_ + 4 * cc_, (kB_ + 4 * cc_ < Ktot));           \
    }                                                                              \
    if (++kP == KT) { kP = 0; ++sP; }                                              \
} while (0)

    // prologue: stages 0 and 1
    ISSUE(0);
    cp_commit();
    if (len > 1) { ISSUE(1); }
    cp_commit();

    for (int j = 0; j < len; ++j) {
        if (j + 2 <= len) cp_wait1(); else cp_wait0();
        __syncthreads();

        const uint32_t st = sb + (uint32_t)(j & 1) * STAGE_B;

#pragma unroll
        for (int k8 = 0; k8 < BK2; k8 += 8) {
            uint32_t aF[2][4], bF[2][4];
            ldsm4(aF[0][0], aF[0][1], aF[0][2], aF[0][3], st + aAddr0 + k8 * 4);
            ldsm4(aF[1][0], aF[1][1], aF[1][2], aF[1][3], st + aAddr0 + 16 * AP * 4 + k8 * 4);
            ldsm4(bF[0][0], bF[0][1], bF[0][2], bF[0][3], st + bAddr0 + k8 * 4);
            ldsm4(bF[1][0], bF[1][1], bF[1][2], bF[1][3], st + bAddr0 + 16 * AP * 4 + k8 * 4);
#pragma unroll
            for (int mt = 0; mt < 2; ++mt)
#pragma unroll
                for (int i = 0; i < 4; ++i) aF[mt][i] += 0x1000u;
#pragma unroll
            for (int mt = 0; mt < 2; ++mt) {
                mma8(acc[mt][0][0], acc[mt][0][1], acc[mt][0][2], acc[mt][0][3],
                     aF[mt][0], aF[mt][1], aF[mt][2], aF[mt][3], bF[0][0], bF[0][1]);
                mma8(acc[mt][1][0], acc[mt][1][1], acc[mt][1][2], acc[mt][1][3],
                     aF[mt][0], aF[mt][1], aF[mt][2], aF[mt][3], bF[0][2], bF[0][3]);
                mma8(acc[mt][2][0], acc[mt][2][1], acc[mt][2][2], acc[mt][2][3],
                     aF[mt][0], aF[mt][1], aF[mt][2], aF[mt][3], bF[1][0], bF[1][1]);
                mma8(acc[mt][3][0], acc[mt][3][1], acc[mt][3][2], acc[mt][3][3],
                     aF[mt][0], aF[mt][1], aF[mt][2], aF[mt][3], bF[1][2], bF[1][3]);
            }
        }

        bool segEnd = (++kC == KT);
        if (segEnd || j == len - 1) {
            const int p = g - g_of((long long)sC * KT, TOTAL);
            float* dst = part + ((size_t)(sC * PSLOTS + p) * BM) * HID;
#pragma unroll
            for (int mt = 0; mt < 2; ++mt) {
                const int rowA = wm0 + mt * 16 + r;
                const int rowB = rowA + 8;
#pragma unroll
                for (int nt = 0; nt < 4; ++nt) {
                    const int col = wn0 + nt * 8 + 2 * c;
                    *(float2*)(dst + (size_t)rowA * HID + col) =
                        make_float2(acc[mt][nt][0], acc[mt][nt][1]);
                    *(float2*)(dst + (size_t)rowB * HID + col) =
                        make_float2(acc[mt][nt][2], acc[mt][nt][3]);
                }
            }
            if (segEnd) {
                kC = 0; ++sC;
#pragma unroll
                for (int a = 0; a < 2; ++a)
#pragma unroll
                    for (int b = 0; b < 4; ++b)
#pragma unroll
                        for (int d = 0; d < 4; ++d) acc[a][b][d] = 0.f;
            }
        }

        __syncthreads();
        if (j + 2 < len) { ISSUE(j & 1); }
        cp_commit();
    }
#undef ISSUE
}

// ---------------- reduce GEMM1 pieces -> xwT (n-major [2][64][10000], tf32) ----------------
__global__ void reduce_xwT_kernel(const float* __restrict__ part, float* __restrict__ xwT)
{
    __shared__ float st[64][65];
    const int b  = blockIdx.y;
    const int n0 = blockIdx.x * 64;
    const int ty = threadIdx.x >> 5, tx = threadIdx.x & 31;

    const int s = b * MTILES + (n0 >> 7);
    const long long t0 = (long long)s * KT1;
    const int np = g_of(t0 + KT1 - 1, TOT1) - g_of(t0, TOT1) + 1;
    const int rl0 = n0 & 127;
    const float* base = part + ((size_t)(s * PSLOTS) * BM) * HID;

#pragma unroll
    for (int i = 0; i < 8; ++i) {
        const int nl = ty + i * 8;
        float sa = 0.f, sb = 0.f;
        if (n0 + nl < MROWS) {
            const float* q = base + (size_t)(rl0 + nl) * HID;
#pragma unroll 5
            for (int p = 0; p < np; ++p) {
                sa += q[(size_t)p * BM * HID + tx];
                sb += q[(size_t)p * BM * HID + tx + 32];
            }
        }
        st[tx][nl]      = __uint_as_float(f2tf(sa));
        st[tx + 32][nl] = __uint_as_float(f2tf(sb));
    }
    __syncthreads();

    float* o = xwT + (size_t)b * HID * MROWS;
#pragma unroll
    for (int j = 0; j < 8; ++j) {
        const int h = ty + j * 8;
        if (n0 + tx < MROWS)      o[(size_t)h * MROWS + n0 + tx]      = st[h][tx];
        if (n0 + tx + 32 < MROWS) o[(size_t)h * MROWS + n0 + tx + 32] = st[h][tx + 32];
    }
}

// ---------------- fuse: GEMM2 pieces + bias, attention, emb, q ----------------
__global__ void fuse_kernel(const float* __restrict__ part,
                            const float* __restrict__ b1, const float* __restrict__ b2,
                            const float* __restrict__ attnw, const float* __restrict__ clus,
                            float* __restrict__ emb_out, float* __restrict__ q_out, int M)
{
    const int warp = threadIdx.x >> 5;
    const int lane = threadIdx.x & 31;
    const int i = blockIdx.x * 8 + warp;
    if (i >= M) return;

    const int h0 = lane, h1 = lane + 32;
    const int rloc = i & 127;
    const int mt   = i >> 7;

    float e1a = b1[h0], e1b = b1[h1];
    float e2a = b2[h0], e2b = b2[h1];

    {
        const int s = mt;
        const long long t0 = (long long)s * KT2;
        const int np = g_of(t0 + KT2 - 1, TOT2) - g_of(t0, TOT2) + 1;
        const float* base = part + ((size_t)(s * PSLOTS) * BM + rloc) * HID;
#pragma unroll 5
        for (int p = 0; p < np; ++p) {
            e1a += base[(size_t)p * BM * HID + h0];
            e1b += base[(size_t)p * BM * HID + h1];
        }
    }
    {
        const int s = MTILES + mt;
        const long long t0 = (long long)s * KT2;
        const int np = g_of(t0 + KT2 - 1, TOT2) - g_of(t0, TOT2) + 1;
        const float* base = part + ((size_t)(s * PSLOTS) * BM + rloc) * HID;
#pragma unroll 5
        for (int p = 0; p < np; ++p) {
            e2a += base[(size_t)p * BM * HID + h0];
            e2b += base[(size_t)p * BM * HID + h1];
        }
    }

    const float aw0 = attnw[h0], aw1 = attnw[h1];
    float w1 = e1a * aw0 + e1b * aw1;
    float w2 = e2a * aw0 + e2b * aw1;
#pragma unroll
    for (int o = 16; o; o >>= 1) {
        w1 += __shfl_xor_sync(0xffffffffu, w1, o);
        w2 += __shfl_xor_sync(0xffffffffu, w2, o);
    }
    const float mx  = fmaxf(w1, w2);
    const float x1  = expf(w1 - mx);
    const float x2  = expf(w2 - mx);
    const float inv = 1.f / (x1 + x2);
    const float be1 = x1 * inv, be2 = x2 * inv;

    const float ea = be1 * e1a + be2 * e2a;
    const float eb = be1 * e1b + be2 * e2b;
    emb_out[(size_t)i * HID + h0] = ea;
    emb_out[(size_t)i * HID + h1] = eb;

    if (!q_out) return;

    float tq[10];
    float s = 0.f;
#pragma unroll
    for (int k = 0; k < 10; ++k) {
        const float da = ea - clus[k * HID + h0];
        const float db = eb - clus[k * HID + h1];
        float d2 = da * da + db * db;
#pragma unroll
        for (int o = 16; o; o >>= 1) d2 += __shfl_xor_sync(0xffffffffu, d2, o);
        float tk = 1.f / (1.f + d2 * 5.0f);
        tk = __powf(tk, 0.72f);
        tq[k] = tk;
        s += tk;
    }
    if (lane < 10) q_out[(size_t)i * 10 + lane] = tq[lane] / s;
}

extern "C" void kernel_launch(void* const* d_in, const int* in_sizes, int n_in,
                              void* d_out, int out_size)
{
    const float* x    = (const float*)d_in[0];
    const float* adj1 = (const float*)d_in[1];
    const float* adj2 = (const float*)d_in[2];
    const float* W1   = (const float*)d_in[3];
    const float* b1   = (const float*)d_in[4];
    const float* W2   = (const float*)d_in[5];
    const float* b2   = (const float*)d_in[6];
    const float* attn = (const float*)d_in[7];
    const float* clus = (const float*)d_in[8];

    float *xwT, *wT, *part, *embS;
    cudaGetSymbolAddress((void**)&xwT,  g_xwT);
    cudaGetSymbolAddress((void**)&wT,   g_wT);
    cudaGetSymbolAddress((void**)&part, g_part);
    cudaGetSymbolAddress((void**)&embS, g_emb);

    cudaFuncSetAttribute(gemm_ldsm, cudaFuncAttributeMaxDynamicSharedMemorySize, SMEM_G);

    // Prep: W -> tf32, n-major
    prep_wT_kernel<<<(NFEAT * HID + 255) / 256, 256>>>(W1, W2, wT);

    // GEMM1: pieces of x @ W_b   (A=x lda=512, B=wT ldb=512, K=512, 16 tiles/seg)
    gemm_ldsm<<<NC, 256, SMEM_G>>>(x, x, wT, wT + HID * NFEAT, part,
                                   MROWS, 512, 512, 512, KT1, TOT1);

    // Reduce+transpose -> xwT (tf32, n-major)
    dim3 gr((MROWS + 63) / 64, 2);
    reduce_xwT_kernel<<<gr, 256>>>(part, xwT);

    // GEMM2: pieces of adj_b @ xw_b  (A=adj lda=10000, B=xwT ldb=10000, K=10000)
    gemm_ldsm<<<NC, 256, SMEM_G>>>(adj1, adj2, xwT, xwT + HID * MROWS, part,
                                   MROWS, 10000, 10000, 10000, KT2, TOT2);

    // Fuse
    float* out = (float*)d_out;
    float* emb_out;
    float* q_out;
    const int embN = MROWS * HID;
    const int qN   = MROWS * 10;
    if (out_size >= embN + qN)      { emb_out = out;  q_out = out + embN; }
    else if (out_size >= embN)      { emb_out = out;  q_out = nullptr;    }
    else                            { emb_out = embS; q_out = out;        }

    fuse_kernel<<<(MROWS + 7) / 8, 256>>>(part, b1, b2, attn, clus, emb_out, q_out, MROWS);
}

// round 16
// speedup vs baseline: 1.2285x; 1.2285x over previous
#include <cuda_runtime.h>
#include <cstdint>
#include <math.h>

// ---------------- Problem constants ----------------
#define MROWS 10000
#define NFEAT 512
#define HID   64
#define MTILES 79
#define SEGS  (2 * MTILES)      // 158
#define NC    444               // persistent CTAs = 148 SMs x 3
#define PSLOTS 4

// ---------------- GEMM tiling: CTA 128x64, 8 warps (4m x 2n), warp tile 32x32 ----------------
#define BM 128
#define BN 64
#define BK 16
#define AP 20                   // padded row stride (floats): 80B, 16B-aligned, LDSM conflict-free
#define A_SZB (BM * AP * 4)     // 10240 bytes
#define B_SZB (BN * AP * 4)     // 5120 bytes
#define STAGE_B (A_SZB + B_SZB) // 15360
#define STAGES 4
#define SMEM_G (STAGES * STAGE_B)   // 61440 (x3 CTAs = 184KB/SM)

// GEMM1: x@W K=512 -> 32 tiles/seg.  GEMM2: adj@xw K=10000 -> 625 tiles/seg.
#define KT1 32
#define TOT1 ((long long)SEGS * KT1)    // 5056
#define KT2 625
#define TOT2 ((long long)SEGS * KT2)    // 98750

// ---------------- Scratch ----------------
__device__ __align__(16) float g_xwT[2 * HID * MROWS];           // xw n-major, tf32
__device__ __align__(16) float g_wT[2 * HID * NFEAT];            // W n-major, tf32
__device__ __align__(16) float g_part[SEGS * PSLOTS * BM * HID]; // piece partials (20.7MB)
__device__ __align__(16) float g_emb[MROWS * HID];               // fallback emb

// ---------------- helpers ----------------
__device__ __forceinline__ uint32_t f2tf(float x) {
    uint32_t u; asm("cvt.rna.tf32.f32 %0, %1;" : "=r"(u) : "f"(x)); return u;
}
__device__ __forceinline__ int g_of(long long T, long long TOTAL) {
    return (int)(((T + 1) * NC - 1) / TOTAL);
}
__device__ __forceinline__ void cp16(uint32_t dst, const void* src, bool v) {
    const int sz = v ? 16 : 0;
    asm volatile("cp.async.cg.shared.global [%0], [%1], 16, %2;\n" :: "r"(dst), "l"(src), "r"(sz));
}
__device__ __forceinline__ void cp_commit() { asm volatile("cp.async.commit_group;\n"); }
__device__ __forceinline__ void cp_wait2()  { asm volatile("cp.async.wait_group 2;\n"); }

__device__ __forceinline__ void ldsm4(uint32_t& d0, uint32_t& d1, uint32_t& d2, uint32_t& d3,
                                      uint32_t a) {
    asm volatile("ldmatrix.sync.aligned.m8n8.x4.shared.b16 {%0,%1,%2,%3}, [%4];"
                 : "=r"(d0), "=r"(d1), "=r"(d2), "=r"(d3) : "r"(a));
}
__device__ __forceinline__ void mma8(float& c0, float& c1, float& c2, float& c3,
                                     uint32_t a0, uint32_t a1, uint32_t a2, uint32_t a3,
                                     uint32_t b0, uint32_t b1) {
    asm("mma.sync.aligned.m16n8k8.row.col.f32.tf32.tf32.f32 "
        "{%0,%1,%2,%3}, {%4,%5,%6,%7}, {%8,%9}, {%0,%1,%2,%3};"
        : "+f"(c0), "+f"(c1), "+f"(c2), "+f"(c3)
        : "r"(a0), "r"(a1), "r"(a2), "r"(a3), "r"(b0), "r"(b1));
}

// ---------------- prep: W -> tf32, n-major [2][64][512] ----------------
__global__ void prep_wT_kernel(const float* __restrict__ W1, const float* __restrict__ W2,
                               float* __restrict__ wT)
{
    const int i = blockIdx.x * blockDim.x + threadIdx.x;
    if (i < NFEAT * HID) {
        const int k = i >> 6, n = i & 63;
        wT[n * NFEAT + k]               = __uint_as_float(f2tf(W1[i]));
        wT[HID * NFEAT + n * NFEAT + k] = __uint_as_float(f2tf(W2[i]));
    }
}

// ---------------- persistent GEMM: 4-stage cp.async + ldmatrix tf32 ----------------
// A row-major [M x Ktot] (lda), B n-major [64 x Ktot] (ldb), pre-rounded tf32.
// A frags +0x1000 (HW truncation -> RNA).
__global__ __launch_bounds__(256, 3)
void gemm_ldsm(const float* __restrict__ A0, const float* __restrict__ A1,
               const float* __restrict__ B0, const float* __restrict__ B1,
               float* __restrict__ part, int M, long long lda, long long ldb,
               int Ktot, int KT, long long TOTAL)
{
    extern __shared__ __align__(128) char smem[];
    const uint32_t sb = (uint32_t)__cvta_generic_to_shared(smem);

    const int g = blockIdx.x;
    const long long rngS = ((long long)g * TOTAL) / NC;
    const long long rngE = ((long long)(g + 1) * TOTAL) / NC;

    const int tid   = threadIdx.x;
    const int lane  = tid & 31;
    const int warp  = tid >> 5;
    const int wm0   = (warp & 3) * 32;
    const int wn0   = (warp >> 2) * 32;
    const int r     = lane >> 2;
    const int c     = lane & 3;
    const int matid = lane >> 3;
    const int rr    = lane & 7;

    // LDSM per-lane byte offsets within a stage (verified mapping, R14)
    const uint32_t aOff = ((wm0 + (matid & 1) * 8 + rr) * AP + (matid >> 1) * 4) * 4;
    const uint32_t bOff = (uint32_t)A_SZB + ((wn0 + matid * 8 + rr) * AP) * 4;

    // staging maps: A 512 chunks (2/thread), B 256 chunks (1/thread)
    const int aRow = tid >> 1;              // 0..127
    const int aC0  = (tid & 1) * 8;         // float offset 0 or 8
    const int bRow = tid >> 2;              // 0..63
    const int bC   = (tid & 3) * 4;         // float offset
    const uint32_t dA = sb + (aRow * AP + aC0) * 4;
    const uint32_t dB = sb + (uint32_t)A_SZB + (bRow * AP + bC) * 4;

    long long cur = rngS;
    while (cur < rngE) {
        const int s  = (int)(cur / KT);
        const int k0 = (int)(cur % KT);
        const int kc = (int)min((long long)(KT - k0), rngE - cur);
        const int p  = g - g_of((long long)s * KT, TOTAL);
        const int br = s / MTILES;
        const int mt = s % MTILES;
        const int m0 = mt * BM;
        const int kBase = k0 * BK;

        const float* A = br ? A1 : A0;
        const float* B = br ? B1 : B0;

        const int  arow = m0 + aRow;
        const bool av   = arow < M;
        const float* gA = A + (size_t)(av ? arow : 0) * lda + kBase + aC0;
        const float* gB = B + (size_t)bRow * ldb + kBase + bC;

        float acc[2][4][4];
#pragma unroll
        for (int a = 0; a < 2; ++a)
#pragma unroll
            for (int b = 0; b < 4; ++b)
#pragma unroll
                for (int d = 0; d < 4; ++d) acc[a][b][d] = 0.f;

        __syncthreads();        // previous chunk's smem reads complete

        // prologue: fill STAGES-1 stages
#pragma unroll
        for (int st = 0; st < STAGES - 1; ++st) {
            if (st < kc) {
                const uint32_t so = st * (uint32_t)STAGE_B;
                const int kb = kBase + st * BK;
                cp16(dA + so,      gA + st * BK,     av && (kb + aC0 < Ktot));
                cp16(dA + so + 16, gA + st * BK + 4, av && (kb + aC0 + 4 < Ktot));
                cp16(dB + so,      gB + st * BK,     (kb + bC < Ktot));
            }
            cp_commit();
        }

        int rd = 0, wr = STAGES - 1;

        for (int t = 0; t < kc; ++t) {
            cp_wait2();
            __syncthreads();

            {   // prefetch tile t+STAGES-1 (issued BEFORE compute)
                const int tt = t + STAGES - 1;
                if (tt < kc) {
                    const uint32_t so = wr * (uint32_t)STAGE_B;
                    const int kb = kBase + tt * BK;
                    cp16(dA + so,      gA + tt * BK,     av && (kb + aC0 < Ktot));
                    cp16(dA + so + 16, gA + tt * BK + 4, av && (kb + aC0 + 4 < Ktot));
                    cp16(dB + so,      gB + tt * BK,     (kb + bC < Ktot));
                }
                cp_commit();
                if (++wr == STAGES) wr = 0;
            }

            const uint32_t st = sb + rd * (uint32_t)STAGE_B;
            if (++rd == STAGES) rd = 0;

#pragma unroll
            for (int ks = 0; ks < 2; ++ks) {
                uint32_t aF[2][4], bF[4][2];
                // A: two LDSM.x4 (mt=0,1); matrices (oct0,kq0),(oct1,kq0),(oct0,kq1),(oct1,kq1)
                ldsm4(aF[0][0], aF[0][1], aF[0][2], aF[0][3], st + aOff + ks * 32);
                ldsm4(aF[1][0], aF[1][1], aF[1][2], aF[1][3],
                      st + aOff + 16 * AP * 4 + ks * 32);
                // B: two LDSM.x4 (k-quads 2ks, 2ks+1); matrices = n-octs 0..3
                ldsm4(bF[0][0], bF[1][0], bF[2][0], bF[3][0], st + bOff + (2 * ks) * 16);
                ldsm4(bF[0][1], bF[1][1], bF[2][1], bF[3][1], st + bOff + (2 * ks + 1) * 16);
#pragma unroll
                for (int mt_ = 0; mt_ < 2; ++mt_)
#pragma unroll
                    for (int i = 0; i < 4; ++i) aF[mt_][i] += 0x1000u;
#pragma unroll
                for (int mt_ = 0; mt_ < 2; ++mt_)
#pragma unroll
                    for (int nt = 0; nt < 4; ++nt)
                        mma8(acc[mt_][nt][0], acc[mt_][nt][1], acc[mt_][nt][2], acc[mt_][nt][3],
                             aF[mt_][0], aF[mt_][1], aF[mt_][2], aF[mt_][3],
                             bF[nt][0], bF[nt][1]);
            }
        }

        // flush piece (OOB rows hold zeros; reducers ignore them)
        float* dst = part + ((size_t)(s * PSLOTS + p) * BM) * HID;
#pragma unroll
        for (int mt_ = 0; mt_ < 2; ++mt_) {
            const int rowA = wm0 + mt_ * 16 + r;
            const int rowB = rowA + 8;
#pragma unroll
            for (int nt = 0; nt < 4; ++nt) {
                const int col = wn0 + nt * 8 + 2 * c;
                *(float2*)(dst + (size_t)rowA * HID + col) =
                    make_float2(acc[mt_][nt][0], acc[mt_][nt][1]);
                *(float2*)(dst + (size_t)rowB * HID + col) =
                    make_float2(acc[mt_][nt][2], acc[mt_][nt][3]);
            }
        }

        cur += kc;
    }
}

// ---------------- reduce GEMM1 pieces -> xwT (n-major [2][64][10000], tf32) ----------------
__global__ void reduce_xwT_kernel(const float* __restrict__ part, float* __restrict__ xwT)
{
    __shared__ float st[64][65];
    const int b  = blockIdx.y;
    const int n0 = blockIdx.x * 64;
    const int ty = threadIdx.x >> 5, tx = threadIdx.x & 31;

    const int s = b * MTILES + (n0 >> 7);
    const long long t0 = (long long)s * KT1;
    const int np = g_of(t0 + KT1 - 1, TOT1) - g_of(t0, TOT1) + 1;
    const int rl0 = n0 & 127;
    const float* base = part + ((size_t)(s * PSLOTS) * BM) * HID;

#pragma unroll
    for (int i = 0; i < 8; ++i) {
        const int nl = ty + i * 8;
        float sa = 0.f, sb = 0.f;
        if (n0 + nl < MROWS) {
            const float* q = base + (size_t)(rl0 + nl) * HID;
#pragma unroll 4
            for (int p = 0; p < np; ++p) {
                sa += q[(size_t)p * BM * HID + tx];
                sb += q[(size_t)p * BM * HID + tx + 32];
            }
        }
        st[tx][nl]      = __uint_as_float(f2tf(sa));
        st[tx + 32][nl] = __uint_as_float(f2tf(sb));
    }
    __syncthreads();

    float* o = xwT + (size_t)b * HID * MROWS;
#pragma unroll
    for (int j = 0; j < 8; ++j) {
        const int h = ty + j * 8;
        if (n0 + tx < MROWS)      o[(size_t)h * MROWS + n0 + tx]      = st[h][tx];
        if (n0 + tx + 32 < MROWS) o[(size_t)h * MROWS + n0 + tx + 32] = st[h][tx + 32];
    }
}

// ---------------- fuse: GEMM2 pieces + bias, attention, emb, q ----------------
__global__ void fuse_kernel(const float* __restrict__ part,
                            const float* __restrict__ b1, const float* __restrict__ b2,
                            const float* __restrict__ attnw, const float* __restrict__ clus,
                            float* __restrict__ emb_out, float* __restrict__ q_out, int M)
{
    const int warp = threadIdx.x >> 5;
    const int lane = threadIdx.x & 31;
    const int i = blockIdx.x * 8 + warp;
    if (i >= M) return;

    const int h0 = lane, h1 = lane + 32;
    const int rloc = i & 127;
    const int mt   = i >> 7;

    float e1a = b1[h0], e1b = b1[h1];
    float e2a = b2[h0], e2b = b2[h1];

    {
        const int s = mt;
        const long long t0 = (long long)s * KT2;
        const int np = g_of(t0 + KT2 - 1, TOT2) - g_of(t0, TOT2) + 1;
        const float* base = part + ((size_t)(s * PSLOTS) * BM + rloc) * HID;
#pragma unroll 4
        for (int p = 0; p < np; ++p) {
            e1a += base[(size_t)p * BM * HID + h0];
            e1b += base[(size_t)p * BM * HID + h1];
        }
    }
    {
        const int s = MTILES + mt;
        const long long t0 = (long long)s * KT2;
        const int np = g_of(t0 + KT2 - 1, TOT2) - g_of(t0, TOT2) + 1;
        const float* base = part + ((size_t)(s * PSLOTS) * BM + rloc) * HID;
#pragma unroll 4
        for (int p = 0; p < np; ++p) {
            e2a += base[(size_t)p * BM * HID + h0];
            e2b += base[(size_t)p * BM * HID + h1];
        }
    }

    const float aw0 = attnw[h0], aw1 = attnw[h1];
    float w1 = e1a * aw0 + e1b * aw1;
    float w2 = e2a * aw0 + e2b * aw1;
#pragma unroll
    for (int o = 16; o; o >>= 1) {
        w1 += __shfl_xor_sync(0xffffffffu, w1, o);
        w2 += __shfl_xor_sync(0xffffffffu, w2, o);
    }
    const float mx  = fmaxf(w1, w2);
    const float x1  = expf(w1 - mx);
    const float x2  = expf(w2 - mx);
    const float inv = 1.f / (x1 + x2);
    const float be1 = x1 * inv, be2 = x2 * inv;

    const float ea = be1 * e1a + be2 * e2a;
    const float eb = be1 * e1b + be2 * e2b;
    emb_out[(size_t)i * HID + h0] = ea;
    emb_out[(size_t)i * HID + h1] = eb;

    if (!q_out) return;

    float tq[10];
    float s = 0.f;
#pragma unroll
    for (int k = 0; k < 10; ++k) {
        const float da = ea - clus[k * HID + h0];
        const float db = eb - clus[k * HID + h1];
        float d2 = da * da + db * db;
#pragma unroll
        for (int o = 16; o; o >>= 1) d2 += __shfl_xor_sync(0xffffffffu, d2, o);
        float tk = 1.f / (1.f + d2 * 5.0f);
        tk = __powf(tk, 0.72f);
        tq[k] = tk;
        s += tk;
    }
    if (lane < 10) q_out[(size_t)i * 10 + lane] = tq[lane] / s;
}

extern "C" void kernel_launch(void* const* d_in, const int* in_sizes, int n_in,
                              void* d_out, int out_size)
{
    const float* x    = (const float*)d_in[0];
    const float* adj1 = (const float*)d_in[1];
    const float* adj2 = (const float*)d_in[2];
    const float* W1   = (const float*)d_in[3];
    const float* b1   = (const float*)d_in[4];
    const float* W2   = (const float*)d_in[5];
    const float* b2   = (const float*)d_in[6];
    const float* attn = (const float*)d_in[7];
    const float* clus = (const float*)d_in[8];

    float *xwT, *wT, *part, *embS;
    cudaGetSymbolAddress((void**)&xwT,  g_xwT);
    cudaGetSymbolAddress((void**)&wT,   g_wT);
    cudaGetSymbolAddress((void**)&part, g_part);
    cudaGetSymbolAddress((void**)&embS, g_emb);

    cudaFuncSetAttribute(gemm_ldsm, cudaFuncAttributeMaxDynamicSharedMemorySize, SMEM_G);

    // Prep: W -> tf32, n-major
    prep_wT_kernel<<<(NFEAT * HID + 255) / 256, 256>>>(W1, W2, wT);

    // GEMM1: pieces of x @ W_b   (A=x lda=512, B=wT ldb=512, K=512)
    gemm_ldsm<<<NC, 256, SMEM_G>>>(x, x, wT, wT + HID * NFEAT, part,
                                   MROWS, 512, 512, 512, KT1, TOT1);

    // Reduce+transpose -> xwT (tf32, n-major)
    dim3 gr((MROWS + 63) / 64, 2);
    reduce_xwT_kernel<<<gr, 256>>>(part, xwT);

    // GEMM2: pieces of adj_b @ xw_b  (A=adj lda=10000, B=xwT ldb=10000, K=10000)
    gemm_ldsm<<<NC, 256, SMEM_G>>>(adj1, adj2, xwT, xwT + HID * MROWS, part,
                                   MROWS, 10000, 10000, 10000, KT2, TOT2);

    // Fuse
    float* out = (float*)d_out;
    float* emb_out;
    float* q_out;
    const int embN = MROWS * HID;
    const int qN   = MROWS * 10;
    if (out_size >= embN + qN)      { emb_out = out;  q_out = out + embN; }
    else if (out_size >= embN)      { emb_out = out;  q_out = nullptr;    }
    else                            { emb_out = embS; q_out = out;        }

    fuse_kernel<<<(MROWS + 7) / 8, 256>>>(part, b1, b2, attn, clus, emb_out, q_out, MROWS);
}